// round 9
// baseline (speedup 1.0000x reference)
#include <cuda_runtime.h>
#include <cuda_bf16.h>
#include <cstdint>

// Problem constants
#define N_OUT 4096
#define N_IN  4096
#define BATCH 4096

// ---------------------------------------------------------------------------
// Static device scratch (allocation-free rule)
// ---------------------------------------------------------------------------
__device__ float g_W[(size_t)N_OUT * N_IN];                 // 64 MB dense W
__device__ __nv_bfloat16 g_Whi[(size_t)N_OUT * N_IN];       // 32 MB
__device__ __nv_bfloat16 g_Wlo[(size_t)N_OUT * N_IN];       // 32 MB
__device__ __nv_bfloat16 g_Bhi[(size_t)BATCH * N_IN];       // 32 MB, [n][k] K-major
__device__ __nv_bfloat16 g_Blo[(size_t)BATCH * N_IN];       // 32 MB

// ---------------------------------------------------------------------------
// Helpers (base-ISA only: cp.async sm_80, ldmatrix sm_75, mma.sync sm_80)
// ---------------------------------------------------------------------------
__device__ __forceinline__ uint32_t smem_u32(const void* p) {
    uint32_t a;
    asm("{ .reg .u64 t; cvta.to.shared.u64 t, %1; cvt.u32.u64 %0, t; }"
        : "=r"(a) : "l"(p));
    return a;
}

__device__ __forceinline__ void cp_async16(uint32_t sdst, const void* gsrc) {
    asm volatile("cp.async.cg.shared.global [%0], [%1], 16;"
                 :: "r"(sdst), "l"(gsrc) : "memory");
}
#define CP_COMMIT() asm volatile("cp.async.commit_group;" ::: "memory")
#define CP_WAIT0()  asm volatile("cp.async.wait_group 0;" ::: "memory")

__device__ __forceinline__ void ldsm_x4(uint32_t r[4], uint32_t addr) {
    asm volatile("ldmatrix.sync.aligned.m8n8.x4.shared.b16 {%0,%1,%2,%3}, [%4];"
                 : "=r"(r[0]), "=r"(r[1]), "=r"(r[2]), "=r"(r[3]) : "r"(addr));
}

__device__ __forceinline__ void mma_bf16(float d[4], const uint32_t a[4],
                                         const uint32_t b[2]) {
    asm volatile(
        "mma.sync.aligned.m16n8k16.row.col.f32.bf16.bf16.f32 "
        "{%0,%1,%2,%3}, {%4,%5,%6,%7}, {%8,%9}, {%0,%1,%2,%3};"
        : "+f"(d[0]), "+f"(d[1]), "+f"(d[2]), "+f"(d[3])
        : "r"(a[0]), "r"(a[1]), "r"(a[2]), "r"(a[3]), "r"(b[0]), "r"(b[1]));
}

// ---------------------------------------------------------------------------
// Kernel 1: zero dense W
// ---------------------------------------------------------------------------
__global__ void zero_W_kernel() {
    float4* p = reinterpret_cast<float4*>(g_W);
    const size_t n4 = (size_t)N_OUT * N_IN / 4;
    size_t i = (size_t)blockIdx.x * blockDim.x + threadIdx.x;
    size_t stride = (size_t)gridDim.x * blockDim.x;
    float4 z = make_float4(0.f, 0.f, 0.f, 0.f);
    for (; i < n4; i += stride) p[i] = z;
}

// ---------------------------------------------------------------------------
// Kernel 2: COO scatter-add
// ---------------------------------------------------------------------------
__global__ void scatter_kernel(const float* __restrict__ values,
                               const int* __restrict__ rows,
                               const int* __restrict__ cols, int nnz) {
    int i = blockIdx.x * blockDim.x + threadIdx.x;
    if (i < nnz) atomicAdd(&g_W[(size_t)rows[i] * N_IN + cols[i]], values[i]);
}

// ---------------------------------------------------------------------------
// Kernel 3: W fp32 -> (hi, lo) bf16 split
// ---------------------------------------------------------------------------
__global__ void convert_W_kernel() {
    const size_t n4 = (size_t)N_OUT * N_IN / 4;
    const float4* src = reinterpret_cast<const float4*>(g_W);
    __nv_bfloat162* hi = reinterpret_cast<__nv_bfloat162*>(g_Whi);
    __nv_bfloat162* lo = reinterpret_cast<__nv_bfloat162*>(g_Wlo);
    size_t i = (size_t)blockIdx.x * blockDim.x + threadIdx.x;
    size_t stride = (size_t)gridDim.x * blockDim.x;
    for (; i < n4; i += stride) {
        float4 w = src[i];
        __nv_bfloat16 hx = __float2bfloat16_rn(w.x);
        __nv_bfloat16 hy = __float2bfloat16_rn(w.y);
        __nv_bfloat16 hz = __float2bfloat16_rn(w.z);
        __nv_bfloat16 hw = __float2bfloat16_rn(w.w);
        __nv_bfloat16 lx = __float2bfloat16_rn(w.x - __bfloat162float(hx));
        __nv_bfloat16 ly = __float2bfloat16_rn(w.y - __bfloat162float(hy));
        __nv_bfloat16 lz = __float2bfloat16_rn(w.z - __bfloat162float(hz));
        __nv_bfloat16 lw = __float2bfloat16_rn(w.w - __bfloat162float(hw));
        hi[2 * i]     = __nv_bfloat162(hx, hy);
        hi[2 * i + 1] = __nv_bfloat162(hz, hw);
        lo[2 * i]     = __nv_bfloat162(lx, ly);
        lo[2 * i + 1] = __nv_bfloat162(lz, lw);
    }
}

// ---------------------------------------------------------------------------
// Kernel 4: inputs [k][n] fp32 -> transposed bf16 (hi, lo) [n][k]
// ---------------------------------------------------------------------------
__global__ void convert_B_kernel(const float* __restrict__ inp) {
    __shared__ float ts[32][33];
    int n0 = blockIdx.x * 32, k0 = blockIdx.y * 32;
    int tx = threadIdx.x, ty = threadIdx.y;   // 32 x 8
    #pragma unroll
    for (int r = ty; r < 32; r += 8)
        ts[r][tx] = inp[(size_t)(k0 + r) * BATCH + n0 + tx];
    __syncthreads();
    #pragma unroll
    for (int r = ty; r < 32; r += 8) {
        float v = ts[tx][r];
        __nv_bfloat16 h = __float2bfloat16_rn(v);
        __nv_bfloat16 l = __float2bfloat16_rn(v - __bfloat162float(h));
        size_t o = (size_t)(n0 + r) * N_IN + k0 + tx;
        g_Bhi[o] = h;
        g_Blo[o] = l;
    }
}

// ---------------------------------------------------------------------------
// Kernel 5: mma.sync split-bf16 GEMM + bias + relu
//   CTA tile 128x256x32, 8 warps (2m x 4n), warp tile 64x64.
//   Double-buffered cp.async. D = Ahi*Bhi + Ahi*Blo + Alo*Bhi (fp32 accum).
//   Two-pass per k16 slab (bh-pass, bl-pass) keeps B-hi/B-lo frags from
//   co-residing -> ~170 regs, no spills.
// ---------------------------------------------------------------------------
#define BM 128
#define BN 256
#define BK 32
#define NCH (N_IN / BK)        // 128 chunks
#define ROWB 80                // 16B-aligned padded row stride, conflict-free
#define A_TILEB (128 * ROWB)   // 10240 B
#define B_TILEB (256 * ROWB)   // 20480 B
#define OFF_AH 0
#define OFF_AL A_TILEB
#define OFF_BH (2 * A_TILEB)
#define OFF_BL (2 * A_TILEB + B_TILEB)
#define STAGEB (2 * A_TILEB + 2 * B_TILEB)   // 61440 B
#define GEMM_SMEM (2 * STAGEB)               // 122880 B

__device__ __forceinline__ void load_chunk(uint32_t sb, int s, int c,
                                           int bm, int bn, int tid) {
    const size_t kof = (size_t)c * BK;
    const __nv_bfloat16* ah = g_Whi + (size_t)bm * N_IN + kof;
    const __nv_bfloat16* al = g_Wlo + (size_t)bm * N_IN + kof;
    const __nv_bfloat16* bh = g_Bhi + (size_t)bn * N_IN + kof;
    const __nv_bfloat16* bl = g_Blo + (size_t)bn * N_IN + kof;
    const uint32_t st = sb + s * STAGEB;
    // A tiles: 128 rows x 4 x 16B -> 512 cp per tile; 2 per thread.
    #pragma unroll
    for (int l = 0; l < 2; l++) {
        int i = tid + l * 256;
        int row = i >> 2;
        int kc = i & 3;
        size_t go = (size_t)row * N_IN + kc * 8;
        uint32_t so = row * ROWB + kc * 16;
        cp_async16(st + OFF_AH + so, ah + go);
        cp_async16(st + OFF_AL + so, al + go);
    }
    // B tiles: 256 rows x 4 x 16B -> 1024 cp per tile; 4 per thread.
    #pragma unroll
    for (int l = 0; l < 4; l++) {
        int i = tid + l * 256;
        int row = i >> 2;
        int kc = i & 3;
        size_t go = (size_t)row * N_IN + kc * 8;
        uint32_t so = row * ROWB + kc * 16;
        cp_async16(st + OFF_BH + so, bh + go);
        cp_async16(st + OFF_BL + so, bl + go);
    }
}

__global__ __launch_bounds__(256)
void gemm_mma_kernel(const float* __restrict__ bias, float* __restrict__ C) {
    extern __shared__ char smem[];
    const uint32_t sb = smem_u32(smem);
    const int tid = threadIdx.x;
    const int wid = tid >> 5, lane = tid & 31;
    const int warp_m = wid >> 2;          // 0..1 -> 64-row slab
    const int warp_n = wid & 3;           // 0..3 -> 64-col slab
    const int bm = blockIdx.y * BM, bn = blockIdx.x * BN;

    float acc[4][8][4];
    #pragma unroll
    for (int mt = 0; mt < 4; mt++)
        #pragma unroll
        for (int nt = 0; nt < 8; nt++)
            #pragma unroll
            for (int r = 0; r < 4; r++) acc[mt][nt][r] = 0.f;

    // Per-lane ldmatrix byte offsets (same frag mapping as round-8, verified).
    const uint32_t aOff = (warp_m * 64 + (lane & 15)) * ROWB + (lane >> 4) * 16;
    const uint32_t bOff = (warp_n * 64 + ((lane >> 4) & 1) * 8 + (lane & 7)) * ROWB
                        + ((lane >> 3) & 1) * 16;

    load_chunk(sb, 0, 0, bm, bn, tid);
    CP_COMMIT();

    for (int c = 0; c < NCH; c++) {
        const int s = c & 1;
        CP_WAIT0();
        __syncthreads();
        if (c + 1 < NCH) {
            load_chunk(sb, s ^ 1, c + 1, bm, bn, tid);
            CP_COMMIT();
        }
        const uint32_t base = sb + s * STAGEB;
        #pragma unroll
        for (int ks = 0; ks < 2; ks++) {
            const uint32_t ko = ks * 32;   // 16 bf16 = 32 B
            uint32_t bfr[4][4];
            // ---- pass 1: B-hi with A-hi and A-lo ----
            #pragma unroll
            for (int j = 0; j < 4; j++)
                ldsm_x4(bfr[j], base + OFF_BH + bOff + j * (16 * ROWB) + ko);
            #pragma unroll
            for (int mt = 0; mt < 4; mt++) {
                uint32_t afr[4];
                ldsm_x4(afr, base + OFF_AH + aOff + mt * (16 * ROWB) + ko);
                #pragma unroll
                for (int nt = 0; nt < 8; nt++)
                    mma_bf16(acc[mt][nt], afr, &bfr[nt >> 1][(nt & 1) * 2]);
                ldsm_x4(afr, base + OFF_AL + aOff + mt * (16 * ROWB) + ko);
                #pragma unroll
                for (int nt = 0; nt < 8; nt++)
                    mma_bf16(acc[mt][nt], afr, &bfr[nt >> 1][(nt & 1) * 2]);
            }
            // ---- pass 2: B-lo with A-hi ----
            #pragma unroll
            for (int j = 0; j < 4; j++)
                ldsm_x4(bfr[j], base + OFF_BL + bOff + j * (16 * ROWB) + ko);
            #pragma unroll
            for (int mt = 0; mt < 4; mt++) {
                uint32_t afr[4];
                ldsm_x4(afr, base + OFF_AH + aOff + mt * (16 * ROWB) + ko);
                #pragma unroll
                for (int nt = 0; nt < 8; nt++)
                    mma_bf16(acc[mt][nt], afr, &bfr[nt >> 1][(nt & 1) * 2]);
            }
        }
        __syncthreads();
    }

    // Epilogue: bias + relu. d0,d1 -> row gid, cols 2tig..; d2,d3 -> row gid+8.
    const int gid = lane >> 2, tig = lane & 3;
    #pragma unroll
    for (int mt = 0; mt < 4; mt++) {
        const int r0 = bm + warp_m * 64 + mt * 16 + gid;
        const int r1 = r0 + 8;
        const float bv0 = bias[r0], bv1 = bias[r1];
        #pragma unroll
        for (int nt = 0; nt < 8; nt++) {
            const int col = bn + warp_n * 64 + nt * 8 + tig * 2;
            float2 v0, v1;
            v0.x = fmaxf(acc[mt][nt][0] + bv0, 0.f);
            v0.y = fmaxf(acc[mt][nt][1] + bv0, 0.f);
            v1.x = fmaxf(acc[mt][nt][2] + bv1, 0.f);
            v1.y = fmaxf(acc[mt][nt][3] + bv1, 0.f);
            *reinterpret_cast<float2*>(C + (size_t)r0 * BATCH + col) = v0;
            *reinterpret_cast<float2*>(C + (size_t)r1 * BATCH + col) = v1;
        }
    }
}

// ---------------------------------------------------------------------------
// kernel_launch
// ---------------------------------------------------------------------------
extern "C" void kernel_launch(void* const* d_in, const int* in_sizes, int n_in,
                              void* d_out, int out_size) {
    const float* inputs = (const float*)d_in[0];
    const float* values = (const float*)d_in[1];
    const float* biases = (const float*)d_in[2];
    const int*   rows   = (const int*)d_in[3];
    const int*   cols   = (const int*)d_in[4];
    float* out = (float*)d_out;
    const int nnz = in_sizes[1];

    cudaFuncSetAttribute(gemm_mma_kernel,
                         cudaFuncAttributeMaxDynamicSharedMemorySize, GEMM_SMEM);

    zero_W_kernel<<<2048, 256>>>();
    scatter_kernel<<<(nnz + 255) / 256, 256>>>(values, rows, cols, nnz);
    convert_W_kernel<<<2048, 256>>>();
    convert_B_kernel<<<dim3(BATCH / 32, N_IN / 32), dim3(32, 8)>>>(inputs);
    gemm_mma_kernel<<<dim3(BATCH / BN, N_OUT / BM), 256, GEMM_SMEM>>>(biases, out);
}

// round 12
// speedup vs baseline: 1.0205x; 1.0205x over previous
#include <cuda_runtime.h>
#include <cuda_bf16.h>
#include <cstdint>

// Problem constants
#define N_OUT 4096
#define N_IN  4096
#define BATCH 4096

// ---------------------------------------------------------------------------
// Static device scratch (allocation-free rule)
// ---------------------------------------------------------------------------
__device__ float g_W[(size_t)N_OUT * N_IN];                 // 64 MB dense W
__device__ __nv_bfloat16 g_Whi[(size_t)N_OUT * N_IN];       // 32 MB
__device__ __nv_bfloat16 g_Wlo[(size_t)N_OUT * N_IN];       // 32 MB
__device__ __nv_bfloat16 g_Bhi[(size_t)BATCH * N_IN];       // 32 MB, [n][k] K-major
__device__ __nv_bfloat16 g_Blo[(size_t)BATCH * N_IN];       // 32 MB

// ---------------------------------------------------------------------------
// Helpers (base-ISA only: cp.async sm_80, ldmatrix sm_75, mma.sync sm_80)
// ---------------------------------------------------------------------------
__device__ __forceinline__ uint32_t smem_u32(const void* p) {
    uint32_t a;
    asm("{ .reg .u64 t; cvta.to.shared.u64 t, %1; cvt.u32.u64 %0, t; }"
        : "=r"(a) : "l"(p));
    return a;
}

__device__ __forceinline__ void cp_async16(uint32_t sdst, const void* gsrc) {
    asm volatile("cp.async.cg.shared.global [%0], [%1], 16;"
                 :: "r"(sdst), "l"(gsrc) : "memory");
}
#define CP_COMMIT() asm volatile("cp.async.commit_group;" ::: "memory")
#define CP_WAIT1()  asm volatile("cp.async.wait_group 1;" ::: "memory")

__device__ __forceinline__ void ldsm_x4(uint32_t r[4], uint32_t addr) {
    asm volatile("ldmatrix.sync.aligned.m8n8.x4.shared.b16 {%0,%1,%2,%3}, [%4];"
                 : "=r"(r[0]), "=r"(r[1]), "=r"(r[2]), "=r"(r[3]) : "r"(addr));
}

__device__ __forceinline__ void mma_bf16(float d[4], const uint32_t a[4],
                                         const uint32_t b[2]) {
    asm volatile(
        "mma.sync.aligned.m16n8k16.row.col.f32.bf16.bf16.f32 "
        "{%0,%1,%2,%3}, {%4,%5,%6,%7}, {%8,%9}, {%0,%1,%2,%3};"
        : "+f"(d[0]), "+f"(d[1]), "+f"(d[2]), "+f"(d[3])
        : "r"(a[0]), "r"(a[1]), "r"(a[2]), "r"(a[3]), "r"(b[0]), "r"(b[1]));
}

// ---------------------------------------------------------------------------
// Kernel 1: zero dense W
// ---------------------------------------------------------------------------
__global__ void zero_W_kernel() {
    float4* p = reinterpret_cast<float4*>(g_W);
    const size_t n4 = (size_t)N_OUT * N_IN / 4;
    size_t i = (size_t)blockIdx.x * blockDim.x + threadIdx.x;
    size_t stride = (size_t)gridDim.x * blockDim.x;
    float4 z = make_float4(0.f, 0.f, 0.f, 0.f);
    for (; i < n4; i += stride) p[i] = z;
}

// ---------------------------------------------------------------------------
// Kernel 2: COO scatter-add
// ---------------------------------------------------------------------------
__global__ void scatter_kernel(const float* __restrict__ values,
                               const int* __restrict__ rows,
                               const int* __restrict__ cols, int nnz) {
    int i = blockIdx.x * blockDim.x + threadIdx.x;
    if (i < nnz) atomicAdd(&g_W[(size_t)rows[i] * N_IN + cols[i]], values[i]);
}

// ---------------------------------------------------------------------------
// Kernel 3: W fp32 -> (hi, lo) bf16 split
// ---------------------------------------------------------------------------
__global__ void convert_W_kernel() {
    const size_t n4 = (size_t)N_OUT * N_IN / 4;
    const float4* src = reinterpret_cast<const float4*>(g_W);
    __nv_bfloat162* hi = reinterpret_cast<__nv_bfloat162*>(g_Whi);
    __nv_bfloat162* lo = reinterpret_cast<__nv_bfloat162*>(g_Wlo);
    size_t i = (size_t)blockIdx.x * blockDim.x + threadIdx.x;
    size_t stride = (size_t)gridDim.x * blockDim.x;
    for (; i < n4; i += stride) {
        float4 w = src[i];
        __nv_bfloat16 hx = __float2bfloat16_rn(w.x);
        __nv_bfloat16 hy = __float2bfloat16_rn(w.y);
        __nv_bfloat16 hz = __float2bfloat16_rn(w.z);
        __nv_bfloat16 hw = __float2bfloat16_rn(w.w);
        __nv_bfloat16 lx = __float2bfloat16_rn(w.x - __bfloat162float(hx));
        __nv_bfloat16 ly = __float2bfloat16_rn(w.y - __bfloat162float(hy));
        __nv_bfloat16 lz = __float2bfloat16_rn(w.z - __bfloat162float(hz));
        __nv_bfloat16 lw = __float2bfloat16_rn(w.w - __bfloat162float(hw));
        hi[2 * i]     = __nv_bfloat162(hx, hy);
        hi[2 * i + 1] = __nv_bfloat162(hz, hw);
        lo[2 * i]     = __nv_bfloat162(lx, ly);
        lo[2 * i + 1] = __nv_bfloat162(lz, lw);
    }
}

// ---------------------------------------------------------------------------
// Kernel 4: inputs [k][n] fp32 -> transposed bf16 (hi, lo) [n][k]
// ---------------------------------------------------------------------------
__global__ void convert_B_kernel(const float* __restrict__ inp) {
    __shared__ float ts[32][33];
    int n0 = blockIdx.x * 32, k0 = blockIdx.y * 32;
    int tx = threadIdx.x, ty = threadIdx.y;   // 32 x 8
    #pragma unroll
    for (int r = ty; r < 32; r += 8)
        ts[r][tx] = inp[(size_t)(k0 + r) * BATCH + n0 + tx];
    __syncthreads();
    #pragma unroll
    for (int r = ty; r < 32; r += 8) {
        float v = ts[tx][r];
        __nv_bfloat16 h = __float2bfloat16_rn(v);
        __nv_bfloat16 l = __float2bfloat16_rn(v - __bfloat162float(h));
        size_t o = (size_t)(n0 + r) * N_IN + k0 + tx;
        g_Bhi[o] = h;
        g_Blo[o] = l;
    }
}

// ---------------------------------------------------------------------------
// Kernel 5: mma.sync split-bf16 GEMM + bias + relu
//   CTA tile 128x256x32, 512 threads = 16 warps (4m x 4n), warp tile 32x64.
//   3-stage cp.async pipeline (wait_group 1); empty tail commits keep the
//   "wait_group 1 => chunk c resident" invariant on the last iterations.
//   D = Ahi*Bhi + Ahi*Blo + Alo*Bhi (fp32 accum).
// ---------------------------------------------------------------------------
#define BM 128
#define BN 256
#define BK 32
#define NCH (N_IN / BK)        // 128 chunks
#define ROWB 80                // 16B-aligned padded row stride, conflict-free
#define A_TILEB (128 * ROWB)   // 10240 B
#define B_TILEB (256 * ROWB)   // 20480 B
#define OFF_AH 0
#define OFF_AL A_TILEB
#define OFF_BH (2 * A_TILEB)
#define OFF_BL (2 * A_TILEB + B_TILEB)
#define STAGEB (2 * A_TILEB + 2 * B_TILEB)   // 61440 B
#define NSTAGE 3
#define GEMM_SMEM (NSTAGE * STAGEB)          // 184320 B

__device__ __forceinline__ void load_chunk(uint32_t sb, int s, int c,
                                           int bm, int bn, int tid) {
    const size_t kof = (size_t)c * BK;
    const __nv_bfloat16* ah = g_Whi + (size_t)bm * N_IN + kof;
    const __nv_bfloat16* al = g_Wlo + (size_t)bm * N_IN + kof;
    const __nv_bfloat16* bh = g_Bhi + (size_t)bn * N_IN + kof;
    const __nv_bfloat16* bl = g_Blo + (size_t)bn * N_IN + kof;
    const uint32_t st = sb + s * STAGEB;
    // A tiles: 512 cp16 each -> 1 per thread.
    {
        int row = tid >> 2;
        int kc = tid & 3;
        size_t go = (size_t)row * N_IN + kc * 8;
        uint32_t so = row * ROWB + kc * 16;
        cp_async16(st + OFF_AH + so, ah + go);
        cp_async16(st + OFF_AL + so, al + go);
    }
    // B tiles: 1024 cp16 each -> 2 per thread.
    #pragma unroll
    for (int l = 0; l < 2; l++) {
        int i = tid + l * 512;
        int row = i >> 2;
        int kc = i & 3;
        size_t go = (size_t)row * N_IN + kc * 8;
        uint32_t so = row * ROWB + kc * 16;
        cp_async16(st + OFF_BH + so, bh + go);
        cp_async16(st + OFF_BL + so, bl + go);
    }
}

__global__ __launch_bounds__(512, 1)
void gemm_mma_kernel(const float* __restrict__ bias, float* __restrict__ C) {
    extern __shared__ char smem[];
    const uint32_t sb = smem_u32(smem);
    const int tid = threadIdx.x;
    const int wid = tid >> 5, lane = tid & 31;
    const int warp_m = wid >> 2;          // 0..3 -> 32-row slab
    const int warp_n = wid & 3;           // 0..3 -> 64-col slab
    const int bm = blockIdx.y * BM, bn = blockIdx.x * BN;

    float acc[2][8][4];
    #pragma unroll
    for (int mt = 0; mt < 2; mt++)
        #pragma unroll
        for (int nt = 0; nt < 8; nt++)
            #pragma unroll
            for (int r = 0; r < 4; r++) acc[mt][nt][r] = 0.f;

    // Per-lane ldmatrix byte offsets (frag mapping verified in round 8).
    const uint32_t aOff = (warp_m * 32 + (lane & 15)) * ROWB + (lane >> 4) * 16;
    const uint32_t bOff = (warp_n * 64 + ((lane >> 4) & 1) * 8 + (lane & 7)) * ROWB
                        + ((lane >> 3) & 1) * 16;

    // Prologue: fill 2 of 3 stages.
    load_chunk(sb, 0, 0, bm, bn, tid);
    CP_COMMIT();
    load_chunk(sb, 1, 1, bm, bn, tid);
    CP_COMMIT();

    for (int c = 0; c < NCH; c++) {
        const int s = c % NSTAGE;
        CP_WAIT1();               // forces chunk c's group complete (see tail commits)
        __syncthreads();
        if (c + 2 < NCH) {
            load_chunk(sb, (c + 2) % NSTAGE, c + 2, bm, bn, tid);
        }
        CP_COMMIT();              // empty group on tail iterations keeps invariant
        const uint32_t base = sb + s * STAGEB;
        #pragma unroll
        for (int ks = 0; ks < 2; ks++) {
            const uint32_t ko = ks * 32;   // 16 bf16 = 32 B
            uint32_t bfr[4][4];
            // ---- pass 1: B-hi with A-hi and A-lo ----
            #pragma unroll
            for (int j = 0; j < 4; j++)
                ldsm_x4(bfr[j], base + OFF_BH + bOff + j * (16 * ROWB) + ko);
            #pragma unroll
            for (int mt = 0; mt < 2; mt++) {
                uint32_t afr[4];
                ldsm_x4(afr, base + OFF_AH + aOff + mt * (16 * ROWB) + ko);
                #pragma unroll
                for (int nt = 0; nt < 8; nt++)
                    mma_bf16(acc[mt][nt], afr, &bfr[nt >> 1][(nt & 1) * 2]);
                ldsm_x4(afr, base + OFF_AL + aOff + mt * (16 * ROWB) + ko);
                #pragma unroll
                for (int nt = 0; nt < 8; nt++)
                    mma_bf16(acc[mt][nt], afr, &bfr[nt >> 1][(nt & 1) * 2]);
            }
            // ---- pass 2: B-lo with A-hi ----
            #pragma unroll
            for (int j = 0; j < 4; j++)
                ldsm_x4(bfr[j], base + OFF_BL + bOff + j * (16 * ROWB) + ko);
            #pragma unroll
            for (int mt = 0; mt < 2; mt++) {
                uint32_t afr[4];
                ldsm_x4(afr, base + OFF_AH + aOff + mt * (16 * ROWB) + ko);
                #pragma unroll
                for (int nt = 0; nt < 8; nt++)
                    mma_bf16(acc[mt][nt], afr, &bfr[nt >> 1][(nt & 1) * 2]);
            }
        }
        __syncthreads();          // stage s free before iter c+1 overwrites it
    }

    // Epilogue: bias + relu.
    const int gid = lane >> 2, tig = lane & 3;
    #pragma unroll
    for (int mt = 0; mt < 2; mt++) {
        const int r0 = bm + warp_m * 32 + mt * 16 + gid;
        const int r1 = r0 + 8;
        const float bv0 = bias[r0], bv1 = bias[r1];
        #pragma unroll
        for (int nt = 0; nt < 8; nt++) {
            const int col = bn + warp_n * 64 + nt * 8 + tig * 2;
            float2 v0, v1;
            v0.x = fmaxf(acc[mt][nt][0] + bv0, 0.f);
            v0.y = fmaxf(acc[mt][nt][1] + bv0, 0.f);
            v1.x = fmaxf(acc[mt][nt][2] + bv1, 0.f);
            v1.y = fmaxf(acc[mt][nt][3] + bv1, 0.f);
            *reinterpret_cast<float2*>(C + (size_t)r0 * BATCH + col) = v0;
            *reinterpret_cast<float2*>(C + (size_t)r1 * BATCH + col) = v1;
        }
    }
}

// ---------------------------------------------------------------------------
// kernel_launch
// ---------------------------------------------------------------------------
extern "C" void kernel_launch(void* const* d_in, const int* in_sizes, int n_in,
                              void* d_out, int out_size) {
    const float* inputs = (const float*)d_in[0];
    const float* values = (const float*)d_in[1];
    const float* biases = (const float*)d_in[2];
    const int*   rows   = (const int*)d_in[3];
    const int*   cols   = (const int*)d_in[4];
    float* out = (float*)d_out;
    const int nnz = in_sizes[1];

    cudaFuncSetAttribute(gemm_mma_kernel,
                         cudaFuncAttributeMaxDynamicSharedMemorySize, GEMM_SMEM);

    zero_W_kernel<<<2048, 256>>>();
    scatter_kernel<<<(nnz + 255) / 256, 256>>>(values, rows, cols, nnz);
    convert_W_kernel<<<2048, 256>>>();
    convert_B_kernel<<<dim3(BATCH / 32, N_IN / 32), dim3(32, 8)>>>(inputs);
    gemm_mma_kernel<<<dim3(BATCH / BN, N_OUT / BM), 512, GEMM_SMEM>>>(biases, out);
}

// round 13
// speedup vs baseline: 1.6429x; 1.6098x over previous
#include <cuda_runtime.h>
#include <cuda_fp16.h>
#include <cstdint>

// Problem constants
#define N_OUT 4096
#define N_IN  4096
#define BATCH 4096

// ---------------------------------------------------------------------------
// Static device scratch (allocation-free rule)
// ---------------------------------------------------------------------------
__device__ float g_W[(size_t)N_OUT * N_IN];           // 64 MB dense W
__device__ __half g_Whi[(size_t)N_OUT * N_IN];        // 32 MB
__device__ __half g_Wlo[(size_t)N_OUT * N_IN];        // 32 MB
__device__ __half g_B[(size_t)BATCH * N_IN];          // 32 MB, [n][k] K-major

// ---------------------------------------------------------------------------
// Helpers (base-ISA only: cp.async sm_80, ldmatrix sm_75, mma.sync sm_80)
// ---------------------------------------------------------------------------
__device__ __forceinline__ uint32_t smem_u32(const void* p) {
    uint32_t a;
    asm("{ .reg .u64 t; cvta.to.shared.u64 t, %1; cvt.u32.u64 %0, t; }"
        : "=r"(a) : "l"(p));
    return a;
}

__device__ __forceinline__ void cp_async16(uint32_t sdst, const void* gsrc) {
    asm volatile("cp.async.cg.shared.global [%0], [%1], 16;"
                 :: "r"(sdst), "l"(gsrc) : "memory");
}
#define CP_COMMIT() asm volatile("cp.async.commit_group;" ::: "memory")
#define CP_WAIT0()  asm volatile("cp.async.wait_group 0;" ::: "memory")

__device__ __forceinline__ void ldsm_x4(uint32_t r[4], uint32_t addr) {
    asm volatile("ldmatrix.sync.aligned.m8n8.x4.shared.b16 {%0,%1,%2,%3}, [%4];"
                 : "=r"(r[0]), "=r"(r[1]), "=r"(r[2]), "=r"(r[3]) : "r"(addr));
}

__device__ __forceinline__ void mma_f16(float d[4], const uint32_t a[4],
                                        const uint32_t b[2]) {
    asm volatile(
        "mma.sync.aligned.m16n8k16.row.col.f32.f16.f16.f32 "
        "{%0,%1,%2,%3}, {%4,%5,%6,%7}, {%8,%9}, {%0,%1,%2,%3};"
        : "+f"(d[0]), "+f"(d[1]), "+f"(d[2]), "+f"(d[3])
        : "r"(a[0]), "r"(a[1]), "r"(a[2]), "r"(a[3]), "r"(b[0]), "r"(b[1]));
}

// ---------------------------------------------------------------------------
// Kernel 1: zero dense W
// ---------------------------------------------------------------------------
__global__ void zero_W_kernel() {
    float4* p = reinterpret_cast<float4*>(g_W);
    const size_t n4 = (size_t)N_OUT * N_IN / 4;
    size_t i = (size_t)blockIdx.x * blockDim.x + threadIdx.x;
    size_t stride = (size_t)gridDim.x * blockDim.x;
    float4 z = make_float4(0.f, 0.f, 0.f, 0.f);
    for (; i < n4; i += stride) p[i] = z;
}

// ---------------------------------------------------------------------------
// Kernel 2: COO scatter-add
// ---------------------------------------------------------------------------
__global__ void scatter_kernel(const float* __restrict__ values,
                               const int* __restrict__ rows,
                               const int* __restrict__ cols, int nnz) {
    int i = blockIdx.x * blockDim.x + threadIdx.x;
    if (i < nnz) atomicAdd(&g_W[(size_t)rows[i] * N_IN + cols[i]], values[i]);
}

// ---------------------------------------------------------------------------
// Kernel 3: W fp32 -> (hi, lo) fp16 split
//   Whi = rn(W); Wlo = rn(W - Whi). Whi+Wlo carries ~22 mantissa bits.
// ---------------------------------------------------------------------------
__global__ void convert_W_kernel() {
    const size_t n4 = (size_t)N_OUT * N_IN / 4;
    const float4* src = reinterpret_cast<const float4*>(g_W);
    __half2* hi = reinterpret_cast<__half2*>(g_Whi);
    __half2* lo = reinterpret_cast<__half2*>(g_Wlo);
    size_t i = (size_t)blockIdx.x * blockDim.x + threadIdx.x;
    size_t stride = (size_t)gridDim.x * blockDim.x;
    for (; i < n4; i += stride) {
        float4 w = src[i];
        __half hx = __float2half_rn(w.x);
        __half hy = __float2half_rn(w.y);
        __half hz = __float2half_rn(w.z);
        __half hw = __float2half_rn(w.w);
        __half lx = __float2half_rn(w.x - __half2float(hx));
        __half ly = __float2half_rn(w.y - __half2float(hy));
        __half lz = __float2half_rn(w.z - __half2float(hz));
        __half lw = __float2half_rn(w.w - __half2float(hw));
        hi[2 * i]     = __halves2half2(hx, hy);
        hi[2 * i + 1] = __halves2half2(hz, hw);
        lo[2 * i]     = __halves2half2(lx, ly);
        lo[2 * i + 1] = __halves2half2(lz, lw);
    }
}

// ---------------------------------------------------------------------------
// Kernel 4: inputs [k][n] fp32 -> transposed single fp16 [n][k]
// ---------------------------------------------------------------------------
__global__ void convert_B_kernel(const float* __restrict__ inp) {
    __shared__ float ts[32][33];
    int n0 = blockIdx.x * 32, k0 = blockIdx.y * 32;
    int tx = threadIdx.x, ty = threadIdx.y;   // 32 x 8
    #pragma unroll
    for (int r = ty; r < 32; r += 8)
        ts[r][tx] = inp[(size_t)(k0 + r) * BATCH + n0 + tx];
    __syncthreads();
    #pragma unroll
    for (int r = ty; r < 32; r += 8) {
        float v = ts[tx][r];                  // = inp[k0+tx][n0+r]
        g_B[(size_t)(n0 + r) * N_IN + k0 + tx] = __float2half_rn(v);
    }
}

// ---------------------------------------------------------------------------
// Kernel 5: mma.sync split-fp16 GEMM + bias + relu
//   128x128x32 CTA tile, 8 warps (warp tile 64x32), double-buffered cp.async.
//   D = Whi*B + Wlo*B (fp32 accum). Proven round-8 structure; 3 tiles/stage.
// ---------------------------------------------------------------------------
#define BM 128
#define BN 128
#define BK 32
#define NCH (N_IN / BK)        // 128 chunks
#define ROWB 80                // padded row stride: conflict-free ldmatrix
#define TILEB (128 * ROWB)     // 10240 B per tile
#define STAGEB (3 * TILEB)     // Ahi, Alo, B
#define OFF_AH 0
#define OFF_AL TILEB
#define OFF_B  (2 * TILEB)
#define GEMM_SMEM (2 * STAGEB) // 61440 B

__device__ __forceinline__ void load_chunk(uint32_t sb, int s, int c,
                                           int bm, int bn, int tid) {
    const size_t kof = (size_t)c * BK;
    const __half* ah = g_Whi + (size_t)bm * N_IN + kof;
    const __half* al = g_Wlo + (size_t)bm * N_IN + kof;
    const __half* b  = g_B   + (size_t)bn * N_IN + kof;
    const uint32_t st = sb + s * STAGEB;
    #pragma unroll
    for (int l = 0; l < 2; l++) {
        int i = tid + l * 256;
        int row = i >> 2;
        int kc = i & 3;
        size_t go = (size_t)row * N_IN + kc * 8;
        uint32_t so = row * ROWB + kc * 16;
        cp_async16(st + OFF_AH + so, ah + go);
        cp_async16(st + OFF_AL + so, al + go);
        cp_async16(st + OFF_B  + so, b  + go);
    }
}

__global__ __launch_bounds__(256, 2)
void gemm_mma_kernel(const float* __restrict__ bias, float* __restrict__ C) {
    extern __shared__ char smem[];
    const uint32_t sb = smem_u32(smem);
    const int tid = threadIdx.x;
    const int wid = tid >> 5, lane = tid & 31;
    const int warp_m = wid >> 2;          // 0..1  -> 64-row slab
    const int warp_n = wid & 3;           // 0..3  -> 32-col slab
    const int bm = blockIdx.y * BM, bn = blockIdx.x * BN;

    float acc[4][4][4];
    #pragma unroll
    for (int mt = 0; mt < 4; mt++)
        #pragma unroll
        for (int nt = 0; nt < 4; nt++)
            #pragma unroll
            for (int r = 0; r < 4; r++) acc[mt][nt][r] = 0.f;

    // Per-lane ldmatrix byte offsets (frag mapping verified in round 8).
    const uint32_t aOff = (warp_m * 64 + (lane & 15)) * ROWB + (lane >> 4) * 16;
    const uint32_t bOff = (warp_n * 32 + ((lane >> 4) & 1) * 8 + (lane & 7)) * ROWB
                        + ((lane >> 3) & 1) * 16;

    load_chunk(sb, 0, 0, bm, bn, tid);
    CP_COMMIT();

    for (int c = 0; c < NCH; c++) {
        const int s = c & 1;
        CP_WAIT0();
        __syncthreads();
        if (c + 1 < NCH) {
            load_chunk(sb, s ^ 1, c + 1, bm, bn, tid);
            CP_COMMIT();
        }
        const uint32_t base = sb + s * STAGEB;
        #pragma unroll
        for (int ks = 0; ks < 2; ks++) {
            const uint32_t ko = ks * 32;   // 16 f16 = 32 B
            uint32_t bfr[2][4];
            #pragma unroll
            for (int j = 0; j < 2; j++)
                ldsm_x4(bfr[j], base + OFF_B + bOff + j * (16 * ROWB) + ko);
            #pragma unroll
            for (int mt = 0; mt < 4; mt++) {
                uint32_t afr[4];
                ldsm_x4(afr, base + OFF_AH + aOff + mt * (16 * ROWB) + ko);
                #pragma unroll
                for (int nt = 0; nt < 4; nt++)
                    mma_f16(acc[mt][nt], afr, &bfr[nt >> 1][(nt & 1) * 2]);
                ldsm_x4(afr, base + OFF_AL + aOff + mt * (16 * ROWB) + ko);
                #pragma unroll
                for (int nt = 0; nt < 4; nt++)
                    mma_f16(acc[mt][nt], afr, &bfr[nt >> 1][(nt & 1) * 2]);
            }
        }
        __syncthreads();
    }

    // Epilogue: bias + relu. d0,d1 -> row gid cols 2tig..; d2,d3 -> row gid+8.
    const int gid = lane >> 2, tig = lane & 3;
    #pragma unroll
    for (int mt = 0; mt < 4; mt++) {
        const int r0 = bm + warp_m * 64 + mt * 16 + gid;
        const int r1 = r0 + 8;
        const float bv0 = bias[r0], bv1 = bias[r1];
        #pragma unroll
        for (int nt = 0; nt < 4; nt++) {
            const int col = bn + warp_n * 32 + nt * 8 + tig * 2;
            float2 v0, v1;
            v0.x = fmaxf(acc[mt][nt][0] + bv0, 0.f);
            v0.y = fmaxf(acc[mt][nt][1] + bv0, 0.f);
            v1.x = fmaxf(acc[mt][nt][2] + bv1, 0.f);
            v1.y = fmaxf(acc[mt][nt][3] + bv1, 0.f);
            *reinterpret_cast<float2*>(C + (size_t)r0 * BATCH + col) = v0;
            *reinterpret_cast<float2*>(C + (size_t)r1 * BATCH + col) = v1;
        }
    }
}

// ---------------------------------------------------------------------------
// kernel_launch
// ---------------------------------------------------------------------------
extern "C" void kernel_launch(void* const* d_in, const int* in_sizes, int n_in,
                              void* d_out, int out_size) {
    const float* inputs = (const float*)d_in[0];
    const float* values = (const float*)d_in[1];
    const float* biases = (const float*)d_in[2];
    const int*   rows   = (const int*)d_in[3];
    const int*   cols   = (const int*)d_in[4];
    float* out = (float*)d_out;
    const int nnz = in_sizes[1];

    cudaFuncSetAttribute(gemm_mma_kernel,
                         cudaFuncAttributeMaxDynamicSharedMemorySize, GEMM_SMEM);

    zero_W_kernel<<<2048, 256>>>();
    scatter_kernel<<<(nnz + 255) / 256, 256>>>(values, rows, cols, nnz);
    convert_W_kernel<<<2048, 256>>>();
    convert_B_kernel<<<dim3(BATCH / 32, N_IN / 32), dim3(32, 8)>>>(inputs);
    gemm_mma_kernel<<<dim3(BATCH / BN, N_OUT / BM), 256, GEMM_SMEM>>>(biases, out);
}